// round 2
// baseline (speedup 1.0000x reference)
#include <cuda_runtime.h>
#include <math.h>

#define BB   64
#define HH   256
#define DD   256
#define TT   512
#define TL   64
#define NCLS 20

// ---------------- device state (scratch; no allocs allowed) ----------------
// hs arrays are [t][j][b] so warp lanes (consecutive b) coalesce.
__device__ float g_cpf[TT*HH*BB];    // premise fw hidden history
__device__ float g_cpb[TT*HH*BB];    // premise bw hidden history
__device__ float g_chf[TL*HH*BB];    // hyp fw hidden history
__device__ float g_chb[TL*HH*BB];    // hyp bw hidden history
__device__ float g_hagg[2*4*HH*BB];  // ping-pong h, 4 agg scans: [phase][scan][j][b]
__device__ float g_mvp[TT*2*BB];     // matched vec premise: [t][persp][b]
__device__ float g_mvh[TL*2*BB];     // matched vec hyp
__device__ float g_y1[512*BB];       // fc1 output: [n][b]

// grid barrier state (returns to init value after an even barrier count)
__device__ unsigned g_cnt[2];
__device__ volatile unsigned g_sns[2];

__device__ __forceinline__ float sigf(float x) { return 1.f / (1.f + __expf(-x)); }

__device__ __forceinline__ void gridbar(int id, unsigned G, unsigned &ls)
{
    __syncthreads();
    if (threadIdx.x == 0) {
        unsigned ns = ls ^ 1u;
        __threadfence();
        unsigned old = atomicAdd(&g_cnt[id], 1u);
        if (old == G - 1u) {
            g_cnt[id] = 0u;
            __threadfence();
            g_sns[id] = ns;
        } else {
            while (g_sns[id] != ns) { }
        }
        __threadfence();
    }
    __syncthreads();
    ls ^= 1u;
}

// 4-gate dot product over K dims; sW rows stride KK, sXH transposed [k][b] pad 65.
template<int KK>
__device__ __forceinline__ void gate_dot(const float* __restrict__ sW,
                                         const float* __restrict__ sXH,
                                         int jj, int b,
                                         float &a0, float &a1, float &a2, float &a3)
{
    const float* w0 = sW + (jj * 4 + 0) * KK;
    const float* w1 = sW + (jj * 4 + 1) * KK;
    const float* w2 = sW + (jj * 4 + 2) * KK;
    const float* w3 = sW + (jj * 4 + 3) * KK;
    a0 = 0.f; a1 = 0.f; a2 = 0.f; a3 = 0.f;
    #pragma unroll 4
    for (int k = 0; k < KK; k += 4) {
        float x0 = sXH[(k + 0) * 65 + b];
        float x1 = sXH[(k + 1) * 65 + b];
        float x2 = sXH[(k + 2) * 65 + b];
        float x3 = sXH[(k + 3) * 65 + b];
        float4 v0 = *(const float4*)(w0 + k);
        float4 v1 = *(const float4*)(w1 + k);
        float4 v2 = *(const float4*)(w2 + k);
        float4 v3 = *(const float4*)(w3 + k);
        a0 += v0.x * x0 + v0.y * x1 + v0.z * x2 + v0.w * x3;
        a1 += v1.x * x0 + v1.y * x1 + v1.z * x2 + v1.w * x3;
        a2 += v2.x * x0 + v2.y * x1 + v2.z * x2 + v2.w * x3;
        a3 += v3.x * x0 + v3.y * x1 + v3.z * x2 + v3.w * x3;
    }
}

__device__ __forceinline__ float lstm_update(float a0, float a1, float a2, float a3, float &c)
{
    float ig = sigf(a0), fg = sigf(a1), gv = tanhf(a2), og = sigf(a3);
    c = fg * c + ig * gv;
    return og * tanhf(c);
}

// ---------------- persistent context BiLSTM (text + label) ----------------
// 128 CTAs: dir = cta>>6, j0 = (cta&63)*4. 256 threads = 64 b x 4 jj.
__global__ __launch_bounds__(256, 1) void ctx_persist(
    const int* __restrict__ text, const int* __restrict__ label,
    const float* __restrict__ emb,
    const float* __restrict__ Wih_f, const float* __restrict__ Whh_f,
    const float* __restrict__ bih_f, const float* __restrict__ bhh_f,
    const float* __restrict__ Wih_b, const float* __restrict__ Whh_b,
    const float* __restrict__ bih_b, const float* __restrict__ bhh_b)
{
    extern __shared__ float sm[];
    float* sW  = sm;             // [16][512]
    float* sXH = sm + 16 * 512;  // [512][65]

    int cta = blockIdx.x;
    int dir = cta >> 6;
    int j0  = (cta & 63) * 4;
    const float* Wih = dir ? Wih_b : Wih_f;
    const float* Whh = dir ? Whh_b : Whh_f;
    const float* bih = dir ? bih_b : bih_f;
    const float* bhh = dir ? bhh_b : bhh_f;
    float* hsT = dir ? g_cpb : g_cpf;
    float* hsL = dir ? g_chb : g_chf;

    int tid = threadIdx.x;
    int b = tid & 63, jj = tid >> 6;
    int j = j0 + jj;

    // stage weight slice ONCE: 16 gate rows x 512 K
    for (int i = tid; i < 2048; i += 256) {
        int r  = i >> 7;
        int k  = (i & 127) * 4;
        int gr = (r & 3) * 256 + j0 + (r >> 2);
        float4 v;
        if (k < 256) v = *(const float4*)(Wih + (size_t)gr * 256 + k);
        else         v = *(const float4*)(Whh + (size_t)gr * 256 + (k - 256));
        *(float4*)(sW + r * 512 + k) = v;
    }
    float bb0 = bih[j]       + bhh[j];
    float bb1 = bih[256 + j] + bhh[256 + j];
    float bb2 = bih[512 + j] + bhh[512 + j];
    float bb3 = bih[768 + j] + bhh[768 + j];

    float cT = 0.f, cL = 0.f;
    unsigned ls = 0;
    int kq = tid >> 6;

    for (int t = 0; t < TT; t++) {
        // ---- text scan step ----
        int pos = dir ? (TT - 1 - t) : t;
        {
            int tok = __ldg(&text[b * TT + pos]);
            const float* er = emb + (size_t)tok * DD + kq * 64;
            #pragma unroll
            for (int i = 0; i < 64; i += 4) {
                float4 v = *(const float4*)(er + i);
                int k = kq * 64 + i;
                sXH[(k + 0) * 65 + b] = v.x;
                sXH[(k + 1) * 65 + b] = v.y;
                sXH[(k + 2) * 65 + b] = v.z;
                sXH[(k + 3) * 65 + b] = v.w;
            }
            if (t == 0) {
                #pragma unroll 8
                for (int i = 0; i < 64; i++) sXH[(256 + kq * 64 + i) * 65 + b] = 0.f;
            } else {
                int pp = dir ? (pos + 1) : (pos - 1);
                const float* hp = hsT + (size_t)pp * HH * BB;
                #pragma unroll 8
                for (int i = 0; i < 64; i++) {
                    int k = kq * 64 + i;
                    sXH[(256 + k) * 65 + b] = hp[k * BB + b];
                }
            }
        }
        __syncthreads();
        {
            float a0, a1, a2, a3;
            gate_dot<512>(sW, sXH, jj, b, a0, a1, a2, a3);
            float h = lstm_update(a0 + bb0, a1 + bb1, a2 + bb2, a3 + bb3, cT);
            hsT[(size_t)pos * HH * BB + j * BB + b] = h;
        }

        // ---- label scan step (rides along for t < TL) ----
        if (t < TL) {
            int posL = dir ? (TL - 1 - t) : t;
            __syncthreads();
            {
                int tok = __ldg(&label[b * TL + posL]);
                const float* er = emb + (size_t)tok * DD + kq * 64;
                #pragma unroll
                for (int i = 0; i < 64; i += 4) {
                    float4 v = *(const float4*)(er + i);
                    int k = kq * 64 + i;
                    sXH[(k + 0) * 65 + b] = v.x;
                    sXH[(k + 1) * 65 + b] = v.y;
                    sXH[(k + 2) * 65 + b] = v.z;
                    sXH[(k + 3) * 65 + b] = v.w;
                }
                if (t == 0) {
                    #pragma unroll 8
                    for (int i = 0; i < 64; i++) sXH[(256 + kq * 64 + i) * 65 + b] = 0.f;
                } else {
                    int pp = dir ? (posL + 1) : (posL - 1);
                    const float* hp = hsL + (size_t)pp * HH * BB;
                    #pragma unroll 8
                    for (int i = 0; i < 64; i++) {
                        int k = kq * 64 + i;
                        sXH[(256 + k) * 65 + b] = hp[k * BB + b];
                    }
                }
            }
            __syncthreads();
            {
                float a0, a1, a2, a3;
                gate_dot<512>(sW, sXH, jj, b, a0, a1, a2, a3);
                float h = lstm_update(a0 + bb0, a1 + bb1, a2 + bb2, a3 + bb3, cL);
                hsL[(size_t)posL * HH * BB + j * BB + b] = h;
            }
        }

        __threadfence();
        gridbar(0, 128u, ls);   // 512 barriers total (even -> state restored)
    }
}

// ---------------- multi-perspective match (L = 1) ----------------
__global__ void match_kernel(const float* __restrict__ w1, const float* __restrict__ w2)
{
    int bi = blockIdx.x;
    int b  = threadIdx.x;  // 64
    const float *v1f, *v2f, *v1b, *v2b;
    float* outp;
    if (bi < TT) {
        int t = bi;
        v1f = g_cpf + (size_t)t * HH * BB;
        v2f = g_chf + (size_t)(TL - 1) * HH * BB;
        v1b = g_cpb + (size_t)t * HH * BB;
        v2b = g_chb;
        outp = g_mvp + (size_t)t * 2 * BB;
    } else {
        int t = bi - TT;
        v1f = g_chf + (size_t)t * HH * BB;
        v2f = g_cpf + (size_t)(TT - 1) * HH * BB;
        v1b = g_chb + (size_t)t * HH * BB;
        v2b = g_cpb;
        outp = g_mvh + (size_t)t * 2 * BB;
    }
    float n1 = 0, da = 0, db = 0, n2 = 0, ea = 0, eb = 0;
    for (int k = 0; k < HH; k++) {
        float ww = w1[k]; float wq = ww * ww;
        float p = v1f[k * BB + b], q = v2f[k * BB + b];
        n1 += wq * p * q; da += wq * p * p; db += wq * q * q;
        float uu = w2[k]; float uq = uu * uu;
        float r = v1b[k * BB + b], s = v2b[k * BB + b];
        n2 += uq * r * s; ea += uq * r * r; eb += uq * s * s;
    }
    outp[b]      = n1 / fmaxf(sqrtf(da) * sqrtf(db), 1e-8f);
    outp[BB + b] = n2 / fmaxf(sqrtf(ea) * sqrtf(eb), 1e-8f);
}

// ---------------- persistent aggregation BiLSTM (premise + hyp) ----------------
// 128 CTAs: dir = cta>>6, j0 = (cta&63)*4. premise scans = scan dir, hyp = 2+dir.
__global__ __launch_bounds__(256, 1) void agg_persist(
    const float* __restrict__ Wih_f, const float* __restrict__ Whh_f,
    const float* __restrict__ bih_f, const float* __restrict__ bhh_f,
    const float* __restrict__ Wih_b, const float* __restrict__ Whh_b,
    const float* __restrict__ bih_b, const float* __restrict__ bhh_b)
{
    extern __shared__ float sm[];
    float* sW = sm;             // [16][256]
    float* sH = sm + 16 * 256;  // [256][65]

    int cta = blockIdx.x;
    int dir = cta >> 6;
    int j0  = (cta & 63) * 4;
    const float* Wih = dir ? Wih_b : Wih_f;
    const float* Whh = dir ? Whh_b : Whh_f;
    const float* bih = dir ? bih_b : bih_f;
    const float* bhh = dir ? bhh_b : bhh_f;

    int tid = threadIdx.x;
    int b = tid & 63, jj = tid >> 6;
    int j = j0 + jj;
    int kq = tid >> 6;

    for (int i = tid; i < 1024; i += 256) {   // Whh slice once: 16 rows x 64 float4
        int r  = i >> 6;
        int k  = (i & 63) * 4;
        int gr = (r & 3) * 256 + j0 + (r >> 2);
        *(float4*)(sW + r * 256 + k) = *(const float4*)(Whh + (size_t)gr * 256 + k);
    }
    int r0 = j, r1 = 256 + j, r2 = 512 + j, r3 = 768 + j;
    float bb0 = bih[r0] + bhh[r0], bb1 = bih[r1] + bhh[r1];
    float bb2 = bih[r2] + bhh[r2], bb3 = bih[r3] + bhh[r3];
    float wi00 = Wih[r0*2], wi01 = Wih[r0*2+1];
    float wi10 = Wih[r1*2], wi11 = Wih[r1*2+1];
    float wi20 = Wih[r2*2], wi21 = Wih[r2*2+1];
    float wi30 = Wih[r3*2], wi31 = Wih[r3*2+1];

    float cP = 0.f, cH = 0.f;
    unsigned ls = 0;

    for (int t = 0; t < TT; t++) {
        int rp = t & 1, wp = rp ^ 1;

        // ---- premise ----
        int pos = dir ? (TT - 1 - t) : t;
        {
            const float* hp = g_hagg + ((size_t)rp * 4 + dir) * HH * BB;
            if (t == 0) {
                #pragma unroll 8
                for (int i = 0; i < 64; i++) sH[(kq * 64 + i) * 65 + b] = 0.f;
            } else {
                #pragma unroll 8
                for (int i = 0; i < 64; i++) {
                    int k = kq * 64 + i;
                    sH[k * 65 + b] = __ldcg(&hp[k * BB + b]);  // bypass L1: addrs recur mod 2
                }
            }
        }
        __syncthreads();
        {
            float a0, a1, a2, a3;
            gate_dot<256>(sW, sH, jj, b, a0, a1, a2, a3);
            const float* mv = g_mvp + (size_t)pos * 2 * BB;
            float m0 = mv[b], m1 = mv[BB + b];
            float h = lstm_update(a0 + bb0 + m0 * wi00 + m1 * wi01,
                                  a1 + bb1 + m0 * wi10 + m1 * wi11,
                                  a2 + bb2 + m0 * wi20 + m1 * wi21,
                                  a3 + bb3 + m0 * wi30 + m1 * wi31, cP);
            g_hagg[((size_t)wp * 4 + dir) * HH * BB + j * BB + b] = h;
        }

        // ---- hyp (t < TL) ----
        if (t < TL) {
            int posH = dir ? (TL - 1 - t) : t;
            __syncthreads();
            {
                const float* hp = g_hagg + ((size_t)rp * 4 + 2 + dir) * HH * BB;
                if (t == 0) {
                    #pragma unroll 8
                    for (int i = 0; i < 64; i++) sH[(kq * 64 + i) * 65 + b] = 0.f;
                } else {
                    #pragma unroll 8
                    for (int i = 0; i < 64; i++) {
                        int k = kq * 64 + i;
                        sH[k * 65 + b] = __ldcg(&hp[k * BB + b]);
                    }
                }
            }
            __syncthreads();
            {
                float a0, a1, a2, a3;
                gate_dot<256>(sW, sH, jj, b, a0, a1, a2, a3);
                const float* mv = g_mvh + (size_t)posH * 2 * BB;
                float m0 = mv[b], m1 = mv[BB + b];
                float h = lstm_update(a0 + bb0 + m0 * wi00 + m1 * wi01,
                                      a1 + bb1 + m0 * wi10 + m1 * wi11,
                                      a2 + bb2 + m0 * wi20 + m1 * wi21,
                                      a3 + bb3 + m0 * wi30 + m1 * wi31, cH);
                g_hagg[((size_t)wp * 4 + 2 + dir) * HH * BB + j * BB + b] = h;
            }
        }

        __threadfence();
        gridbar(1, 128u, ls);   // 512 barriers total (even)
    }
}

// ---------------- fc1: (64,1024) @ (1024,512)^T, tanh ----------------
// x^T is exactly g_hagg phase 0 = [1024][64] (scan-major = concat order).
__global__ void fc1_kernel(const float* __restrict__ W1, const float* __restrict__ b1)
{
    __shared__ float sw[4 * 1024];
    int tid = threadIdx.x;
    int n0  = blockIdx.x * 4;
    for (int i = tid; i < 1024; i += 256) {
        int r = i >> 8;
        int k = (i & 255) * 4;
        *(float4*)(sw + r * 1024 + k) = *(const float4*)(W1 + (size_t)(n0 + r) * 1024 + k);
    }
    __syncthreads();
    int b = tid & 63, nn = tid >> 6;
    const float* X  = g_hagg;  // phase 0: [1024][64]
    const float* wr = sw + nn * 1024;
    float a0 = 0, a1 = 0, a2 = 0, a3 = 0;
    #pragma unroll 8
    for (int k = 0; k < 1024; k += 4) {
        a0 += X[(k + 0) * BB + b] * wr[k + 0];
        a1 += X[(k + 1) * BB + b] * wr[k + 1];
        a2 += X[(k + 2) * BB + b] * wr[k + 2];
        a3 += X[(k + 3) * BB + b] * wr[k + 3];
    }
    int n = n0 + nn;
    g_y1[n * BB + b] = tanhf(a0 + a1 + a2 + a3 + b1[n]);
}

// ---------------- fc2: (64,512) @ (512,20)^T ----------------
__global__ void fc2_kernel(const float* __restrict__ W2, const float* __restrict__ b2,
                           float* __restrict__ out)
{
    int nc = blockIdx.x;    // 20
    int b  = threadIdx.x;   // 64
    float acc = 0.f;
    #pragma unroll 8
    for (int n = 0; n < 512; n++) acc += g_y1[n * BB + b] * W2[nc * 512 + n];
    out[b * NCLS + nc] = acc + b2[nc];
}

extern "C" void kernel_launch(void* const* d_in, const int* in_sizes, int n_in,
                              void* d_out, int out_size)
{
    const int*   text  = (const int*)d_in[0];
    const int*   label = (const int*)d_in[1];
    const float* emb   = (const float*)d_in[2];
    const float* cWihf = (const float*)d_in[3],  *cWhhf = (const float*)d_in[4];
    const float* cbihf = (const float*)d_in[5],  *cbhhf = (const float*)d_in[6];
    const float* cWihb = (const float*)d_in[7],  *cWhhb = (const float*)d_in[8];
    const float* cbihb = (const float*)d_in[9],  *cbhhb = (const float*)d_in[10];
    const float* mpw1  = (const float*)d_in[11], *mpw2  = (const float*)d_in[12];
    const float* aWihf = (const float*)d_in[13], *aWhhf = (const float*)d_in[14];
    const float* abihf = (const float*)d_in[15], *abhhf = (const float*)d_in[16];
    const float* aWihb = (const float*)d_in[17], *aWhhb = (const float*)d_in[18];
    const float* abihb = (const float*)d_in[19], *abhhb = (const float*)d_in[20];
    const float* W1    = (const float*)d_in[21], *b1    = (const float*)d_in[22];
    const float* W2    = (const float*)d_in[23], *b2    = (const float*)d_in[24];
    float* out = (float*)d_out;

    const int smem_ctx = (16 * 512 + 512 * 65) * 4;  // 165888 B
    const int smem_agg = (16 * 256 + 256 * 65) * 4;  //  82944 B
    cudaFuncSetAttribute(ctx_persist, cudaFuncAttributeMaxDynamicSharedMemorySize, smem_ctx);
    cudaFuncSetAttribute(agg_persist, cudaFuncAttributeMaxDynamicSharedMemorySize, smem_agg);

    ctx_persist<<<128, 256, smem_ctx>>>(text, label, emb,
        cWihf, cWhhf, cbihf, cbhhf, cWihb, cWhhb, cbihb, cbhhb);
    match_kernel<<<TT + TL, 64>>>(mpw1, mpw2);
    agg_persist<<<128, 256, smem_agg>>>(
        aWihf, aWhhf, abihf, abhhf, aWihb, aWhhb, abihb, abhhb);
    fc1_kernel<<<128, 256>>>(W1, b1);
    fc2_kernel<<<20, 64>>>(W2, b2, out);
}

// round 3
// speedup vs baseline: 1.3328x; 1.3328x over previous
#include <cuda_runtime.h>
#include <math.h>

#define BB   64
#define HH   256
#define TT   512
#define TL   64
#define NCLS 20

// ---------------- device state (packed float4 layouts: [t][quad][b]) ----------------
__device__ float4 g_xt[TT*64*64];    // text  x packed
__device__ float4 g_xl[TL*64*64];    // label x packed
__device__ float4 g_hpf[TT*64*64];   // premise fw h
__device__ float4 g_hpb[TT*64*64];   // premise bw h
__device__ float4 g_hlf[TL*64*64];   // hyp fw h
__device__ float4 g_hlb[TL*64*64];   // hyp bw h
__device__ float4 g_hap[3*4*64*64];  // agg h, mod-3 rotation: [phase][scan][q][b]
__device__ float  g_mvp[TT*2*BB];
__device__ float  g_mvh[TL*2*BB];
__device__ float  g_y1[512*BB];
__device__ unsigned g_cflag[128];
__device__ unsigned g_aflag[128];

__device__ __forceinline__ float sigf(float x) { return 1.f / (1.f + __expf(-x)); }

__device__ __forceinline__ unsigned ldacq(const unsigned* p) {
    unsigned v;
    asm volatile("ld.acquire.gpu.u32 %0, [%1];" : "=r"(v) : "l"(p) : "memory");
    return v;
}
__device__ __forceinline__ void strel(unsigned* p, unsigned v) {
    asm volatile("st.release.gpu.u32 [%0], %1;" :: "l"(p), "r"(v) : "memory");
}

__device__ __forceinline__ float lstm_update(float a0, float a1, float a2, float a3, float &c)
{
    float ig = sigf(a0), fg = sigf(a1), gv = tanhf(a2), og = sigf(a3);
    c = fg * c + ig * gv;
    return og * tanhf(c);
}

// 4-gate dot over Q quads; sW rows stride Q*4; sX [q][b] float4.
template<int Q>
__device__ __forceinline__ void gate_dot4(const float* __restrict__ sW,
                                          const float4* __restrict__ sX,
                                          int jj, int b,
                                          float &a0, float &a1, float &a2, float &a3)
{
    const float* w0 = sW + (jj * 4 + 0) * (Q * 4);
    const float* w1 = sW + (jj * 4 + 1) * (Q * 4);
    const float* w2 = sW + (jj * 4 + 2) * (Q * 4);
    const float* w3 = sW + (jj * 4 + 3) * (Q * 4);
    #pragma unroll 4
    for (int q = 0; q < Q; q++) {
        float4 x  = sX[q * 64 + b];
        float4 v0 = *(const float4*)(w0 + q * 4);
        float4 v1 = *(const float4*)(w1 + q * 4);
        float4 v2 = *(const float4*)(w2 + q * 4);
        float4 v3 = *(const float4*)(w3 + q * 4);
        a0 += v0.x * x.x + v0.y * x.y + v0.z * x.z + v0.w * x.w;
        a1 += v1.x * x.x + v1.y * x.y + v1.z * x.z + v1.w * x.w;
        a2 += v2.x * x.x + v2.y * x.y + v2.z * x.z + v2.w * x.w;
        a3 += v3.x * x.x + v3.y * x.y + v3.z * x.z + v3.w * x.w;
    }
}

// ---------------- init: zero flags (each replay) ----------------
__global__ void init_kernel()
{
    int i = threadIdx.x;
    if (i < 128) { g_cflag[i] = 0u; g_aflag[i] = 0u; }
}

// ---------------- pre-gather x = emb[tokens] into packed [t][q][b] ----------------
// grid 576: block tt<512 -> text t=tt; else label t=tt-512. 256 threads.
__global__ void gather_kernel(const int* __restrict__ text, const int* __restrict__ label,
                              const float* __restrict__ emb)
{
    extern __shared__ float sS[];   // [256][65]
    int tt  = blockIdx.x;
    int tid = threadIdx.x, w = tid >> 5, l = tid & 31;
    const int* toks; int T, t; float4* dst;
    if (tt < TT) { toks = text;  T = TT; t = tt;      dst = g_xt; }
    else         { toks = label; T = TL; t = tt - TT; dst = g_xl; }

    for (int bt = w; bt < 64; bt += 8) {
        int tok = toks[bt * T + t];
        const float4* row = (const float4*)(emb + (size_t)tok * 256);
        float4 v0 = row[l], v1 = row[l + 32];
        int k0 = l * 4, k1 = (l + 32) * 4;
        sS[(k0 + 0) * 65 + bt] = v0.x; sS[(k0 + 1) * 65 + bt] = v0.y;
        sS[(k0 + 2) * 65 + bt] = v0.z; sS[(k0 + 3) * 65 + bt] = v0.w;
        sS[(k1 + 0) * 65 + bt] = v1.x; sS[(k1 + 1) * 65 + bt] = v1.y;
        sS[(k1 + 2) * 65 + bt] = v1.z; sS[(k1 + 3) * 65 + bt] = v1.w;
    }
    __syncthreads();
    #pragma unroll
    for (int ii = 0; ii < 16; ii++) {
        int idx = ii * 256 + tid;
        int q = idx >> 6, b = idx & 63;
        float4 o = make_float4(sS[(4*q + 0) * 65 + b], sS[(4*q + 1) * 65 + b],
                               sS[(4*q + 2) * 65 + b], sS[(4*q + 3) * 65 + b]);
        dst[((size_t)t * 64 + q) * 64 + b] = o;
    }
}

// ---------------- persistent context BiLSTM (text + label rides t<64) ----------------
// 128 CTAs: dir = cta>>6, quad qc = cta&63. 256 threads = 64 b x 4 jj.
__global__ __launch_bounds__(256, 1) void ctx_persist(
    const float* __restrict__ Wih_f, const float* __restrict__ Whh_f,
    const float* __restrict__ bih_f, const float* __restrict__ bhh_f,
    const float* __restrict__ Wih_b, const float* __restrict__ Whh_b,
    const float* __restrict__ bih_b, const float* __restrict__ bhh_b)
{
    extern __shared__ float sm[];
    float*  sW = sm;                        // [16][512]
    float4* sX = (float4*)(sm + 16 * 512);  // [128 quads][64 b]
    __shared__ float sTmp[256];

    int cta = blockIdx.x, dir = cta >> 6, qc = cta & 63, j0 = qc * 4;
    const float* Wih = dir ? Wih_b : Wih_f;
    const float* Whh = dir ? Whh_b : Whh_f;
    const float* bih = dir ? bih_b : bih_f;
    const float* bhh = dir ? bhh_b : bhh_f;
    float4* hT = dir ? g_hpb : g_hpf;
    float4* hL = dir ? g_hlb : g_hlf;

    int tid = threadIdx.x;
    int b = tid & 63, jj = tid >> 6;
    int j = j0 + jj;

    for (int i = tid; i < 2048; i += 256) {
        int r = i >> 7, k = (i & 127) * 4;
        int gr = (r & 3) * 256 + j0 + (r >> 2);
        float4 v;
        if (k < 256) v = *(const float4*)(Wih + (size_t)gr * 256 + k);
        else         v = *(const float4*)(Whh + (size_t)gr * 256 + (k - 256));
        *(float4*)(sW + r * 512 + k) = v;
    }
    float bb0 = bih[j]       + bhh[j];
    float bb1 = bih[256 + j] + bhh[256 + j];
    float bb2 = bih[512 + j] + bhh[512 + j];
    float bb3 = bih[768 + j] + bhh[768 + j];

    float cT = 0.f, cL = 0.f;

    for (int t = 0; t < TT; t++) {
        int pos = dir ? (TT - 1 - t) : t;
        // stage x (independent of flags)
        #pragma unroll
        for (int ii = 0; ii < 16; ii++) {
            int idx = ii * 256 + tid; int q = idx >> 6, bb = idx & 63;
            sX[q * 64 + bb] = g_xt[((size_t)pos * 64 + q) * 64 + bb];
        }
        if (t > 0 && tid < 64) {
            const unsigned* f = &g_cflag[dir * 64 + tid];
            while (ldacq(f) < (unsigned)t) { }
        }
        __syncthreads();
        if (t == 0) {
            float4 z = make_float4(0.f, 0.f, 0.f, 0.f);
            #pragma unroll
            for (int ii = 0; ii < 16; ii++) {
                int idx = ii * 256 + tid;
                sX[(64 + (idx >> 6)) * 64 + (idx & 63)] = z;
            }
        } else {
            int pp = dir ? pos + 1 : pos - 1;
            #pragma unroll
            for (int ii = 0; ii < 16; ii++) {
                int idx = ii * 256 + tid; int q = idx >> 6, bb = idx & 63;
                sX[(64 + q) * 64 + bb] = hT[((size_t)pp * 64 + q) * 64 + bb];
            }
        }
        __syncthreads();
        {
            float a0 = bb0, a1 = bb1, a2 = bb2, a3 = bb3;
            gate_dot4<128>(sW, sX, jj, b, a0, a1, a2, a3);
            float h = lstm_update(a0, a1, a2, a3, cT);
            sTmp[b * 4 + jj] = h;
        }
        __syncthreads();
        if (tid < 64) hT[((size_t)pos * 64 + qc) * 64 + tid] = *(float4*)&sTmp[tid * 4];

        if (t < TL) {
            int posL = dir ? (TL - 1 - t) : t;
            #pragma unroll
            for (int ii = 0; ii < 16; ii++) {
                int idx = ii * 256 + tid; int q = idx >> 6, bb = idx & 63;
                sX[q * 64 + bb] = g_xl[((size_t)posL * 64 + q) * 64 + bb];
            }
            if (t == 0) {
                float4 z = make_float4(0.f, 0.f, 0.f, 0.f);
                #pragma unroll
                for (int ii = 0; ii < 16; ii++) {
                    int idx = ii * 256 + tid;
                    sX[(64 + (idx >> 6)) * 64 + (idx & 63)] = z;
                }
            } else {
                int ppL = dir ? posL + 1 : posL - 1;
                #pragma unroll
                for (int ii = 0; ii < 16; ii++) {
                    int idx = ii * 256 + tid; int q = idx >> 6, bb = idx & 63;
                    sX[(64 + q) * 64 + bb] = hL[((size_t)ppL * 64 + q) * 64 + bb];
                }
            }
            __syncthreads();
            {
                float a0 = bb0, a1 = bb1, a2 = bb2, a3 = bb3;
                gate_dot4<128>(sW, sX, jj, b, a0, a1, a2, a3);
                float h = lstm_update(a0, a1, a2, a3, cL);
                sTmp[b * 4 + jj] = h;
            }
            __syncthreads();
            if (tid < 64) hL[((size_t)posL * 64 + qc) * 64 + tid] = *(float4*)&sTmp[tid * 4];
        }

        __syncthreads();
        if (tid == 0) strel(&g_cflag[cta], (unsigned)(t + 1));
    }
}

// ---------------- multi-perspective match (L = 1) ----------------
__global__ void match_kernel(const float* __restrict__ w1, const float* __restrict__ w2)
{
    int bi = blockIdx.x;
    int b  = threadIdx.x;  // 64
    const float4 *v1f, *v2f, *v1b, *v2b;
    float* outp;
    if (bi < TT) {
        int t = bi;
        v1f = g_hpf + (size_t)t * 64 * 64;
        v2f = g_hlf + (size_t)(TL - 1) * 64 * 64;
        v1b = g_hpb + (size_t)t * 64 * 64;
        v2b = g_hlb;
        outp = g_mvp + (size_t)t * 2 * BB;
    } else {
        int t = bi - TT;
        v1f = g_hlf + (size_t)t * 64 * 64;
        v2f = g_hpf + (size_t)(TT - 1) * 64 * 64;
        v1b = g_hlb + (size_t)t * 64 * 64;
        v2b = g_hpb;
        outp = g_mvh + (size_t)t * 2 * BB;
    }
    const float4* w14 = (const float4*)w1;
    const float4* w24 = (const float4*)w2;
    float n1 = 0, da = 0, db = 0, n2 = 0, ea = 0, eb = 0;
    for (int q = 0; q < 64; q++) {
        float4 wv = w14[q];
        float4 p = v1f[q * 64 + b], qq = v2f[q * 64 + b];
        float w2x = wv.x*wv.x, w2y = wv.y*wv.y, w2z = wv.z*wv.z, w2w = wv.w*wv.w;
        n1 += w2x*p.x*qq.x + w2y*p.y*qq.y + w2z*p.z*qq.z + w2w*p.w*qq.w;
        da += w2x*p.x*p.x  + w2y*p.y*p.y  + w2z*p.z*p.z  + w2w*p.w*p.w;
        db += w2x*qq.x*qq.x+ w2y*qq.y*qq.y+ w2z*qq.z*qq.z+ w2w*qq.w*qq.w;
        float4 uv = w24[q];
        float4 r = v1b[q * 64 + b], s = v2b[q * 64 + b];
        float u2x = uv.x*uv.x, u2y = uv.y*uv.y, u2z = uv.z*uv.z, u2w = uv.w*uv.w;
        n2 += u2x*r.x*s.x + u2y*r.y*s.y + u2z*r.z*s.z + u2w*r.w*s.w;
        ea += u2x*r.x*r.x + u2y*r.y*r.y + u2z*r.z*r.z + u2w*r.w*r.w;
        eb += u2x*s.x*s.x + u2y*s.y*s.y + u2z*s.z*s.z + u2w*s.w*s.w;
    }
    outp[b]      = n1 / fmaxf(sqrtf(da) * sqrtf(db), 1e-8f);
    outp[BB + b] = n2 / fmaxf(sqrtf(ea) * sqrtf(eb), 1e-8f);
}

// ---------------- persistent aggregation BiLSTM (premise + hyp rides t<64) ----------------
__global__ __launch_bounds__(256, 1) void agg_persist(
    const float* __restrict__ Wih_f, const float* __restrict__ Whh_f,
    const float* __restrict__ bih_f, const float* __restrict__ bhh_f,
    const float* __restrict__ Wih_b, const float* __restrict__ Whh_b,
    const float* __restrict__ bih_b, const float* __restrict__ bhh_b)
{
    extern __shared__ float sm[];
    float*  sW = sm;                        // [16][256]
    float4* sX = (float4*)(sm + 16 * 256);  // [64 quads][64 b]
    __shared__ float sTmp[256];

    int cta = blockIdx.x, dir = cta >> 6, qc = cta & 63, j0 = qc * 4;
    const float* Wih = dir ? Wih_b : Wih_f;
    const float* Whh = dir ? Whh_b : Whh_f;
    const float* bih = dir ? bih_b : bih_f;
    const float* bhh = dir ? bhh_b : bhh_f;

    int tid = threadIdx.x;
    int b = tid & 63, jj = tid >> 6;
    int j = j0 + jj;

    for (int i = tid; i < 1024; i += 256) {
        int r = i >> 6, k = (i & 63) * 4;
        int gr = (r & 3) * 256 + j0 + (r >> 2);
        *(float4*)(sW + r * 256 + k) = *(const float4*)(Whh + (size_t)gr * 256 + k);
    }
    int r0 = j, r1 = 256 + j, r2 = 512 + j, r3 = 768 + j;
    float bb0 = bih[r0] + bhh[r0], bb1 = bih[r1] + bhh[r1];
    float bb2 = bih[r2] + bhh[r2], bb3 = bih[r3] + bhh[r3];
    float wi00 = Wih[r0*2], wi01 = Wih[r0*2+1];
    float wi10 = Wih[r1*2], wi11 = Wih[r1*2+1];
    float wi20 = Wih[r2*2], wi21 = Wih[r2*2+1];
    float wi30 = Wih[r3*2], wi31 = Wih[r3*2+1];

    float cP = 0.f, cH = 0.f;

    for (int t = 0; t < TT; t++) {
        int wph = t % 3;
        int rph = (t + 2) % 3;   // (t-1) mod 3
        if (t > 0 && tid < 64) {
            const unsigned* f = &g_aflag[dir * 64 + tid];
            while (ldacq(f) < (unsigned)t) { }
        }
        __syncthreads();

        // ---- premise ----
        int pos = dir ? (TT - 1 - t) : t;
        if (t == 0) {
            float4 z = make_float4(0.f, 0.f, 0.f, 0.f);
            #pragma unroll
            for (int ii = 0; ii < 16; ii++) {
                int idx = ii * 256 + tid;
                sX[idx] = z;
            }
        } else {
            const float4* hp = g_hap + ((size_t)rph * 4 + dir) * 4096;
            #pragma unroll
            for (int ii = 0; ii < 16; ii++) {
                int idx = ii * 256 + tid;
                sX[idx] = __ldcg(&hp[idx]);   // addresses recur mod 3 -> bypass L1
            }
        }
        __syncthreads();
        {
            float a0, a1, a2, a3;
            const float* mv = g_mvp + (size_t)pos * 2 * BB;
            float m0 = mv[b], m1 = mv[BB + b];
            a0 = bb0 + m0 * wi00 + m1 * wi01;
            a1 = bb1 + m0 * wi10 + m1 * wi11;
            a2 = bb2 + m0 * wi20 + m1 * wi21;
            a3 = bb3 + m0 * wi30 + m1 * wi31;
            gate_dot4<64>(sW, sX, jj, b, a0, a1, a2, a3);
            float h = lstm_update(a0, a1, a2, a3, cP);
            sTmp[b * 4 + jj] = h;
        }
        __syncthreads();
        if (tid < 64)
            g_hap[((size_t)wph * 4 + dir) * 4096 + qc * 64 + tid] = *(float4*)&sTmp[tid * 4];

        // ---- hyp (t < TL) ----
        if (t < TL) {
            int posH = dir ? (TL - 1 - t) : t;
            if (t == 0) {
                float4 z = make_float4(0.f, 0.f, 0.f, 0.f);
                #pragma unroll
                for (int ii = 0; ii < 16; ii++) sX[ii * 256 + tid] = z;
            } else {
                const float4* hp = g_hap + ((size_t)rph * 4 + 2 + dir) * 4096;
                #pragma unroll
                for (int ii = 0; ii < 16; ii++) {
                    int idx = ii * 256 + tid;
                    sX[idx] = __ldcg(&hp[idx]);
                }
            }
            __syncthreads();
            {
                float a0, a1, a2, a3;
                const float* mv = g_mvh + (size_t)posH * 2 * BB;
                float m0 = mv[b], m1 = mv[BB + b];
                a0 = bb0 + m0 * wi00 + m1 * wi01;
                a1 = bb1 + m0 * wi10 + m1 * wi11;
                a2 = bb2 + m0 * wi20 + m1 * wi21;
                a3 = bb3 + m0 * wi30 + m1 * wi31;
                gate_dot4<64>(sW, sX, jj, b, a0, a1, a2, a3);
                float h = lstm_update(a0, a1, a2, a3, cH);
                sTmp[b * 4 + jj] = h;
            }
            __syncthreads();
            if (tid < 64)
                g_hap[((size_t)wph * 4 + 2 + dir) * 4096 + qc * 64 + tid] = *(float4*)&sTmp[tid * 4];
        }

        __syncthreads();
        if (tid == 0) strel(&g_aflag[cta], (unsigned)(t + 1));
    }
}

// ---------------- fc1: tanh(x @ W1^T + b1) ----------------
// premise final at phase (511%3)=1 (scans 0,1); hyp final at phase (63%3)=0 (scans 2,3).
__global__ void fc1_kernel(const float* __restrict__ W1, const float* __restrict__ b1)
{
    __shared__ float4 sw4[4 * 256];
    int tid = threadIdx.x;
    int n0  = blockIdx.x * 4;
    const float4* W14 = (const float4*)W1;
    for (int i = tid; i < 1024; i += 256) {
        int r = i >> 8, k4 = i & 255;
        sw4[r * 256 + k4] = W14[(size_t)(n0 + r) * 256 + k4];
    }
    __syncthreads();
    int b = tid & 63, nn = tid >> 6;
    float acc = 0.f;
    #pragma unroll
    for (int scan = 0; scan < 4; scan++) {
        int ph = (scan < 2) ? 1 : 0;
        const float4* X = g_hap + ((size_t)ph * 4 + scan) * 4096;
        #pragma unroll 4
        for (int q = 0; q < 64; q++) {
            float4 xv = X[q * 64 + b];
            float4 wv = sw4[nn * 256 + scan * 64 + q];
            acc += xv.x * wv.x + xv.y * wv.y + xv.z * wv.z + xv.w * wv.w;
        }
    }
    int n = n0 + nn;
    g_y1[n * BB + b] = tanhf(acc + b1[n]);
}

// ---------------- fc2 ----------------
__global__ void fc2_kernel(const float* __restrict__ W2, const float* __restrict__ b2,
                           float* __restrict__ out)
{
    int nc = blockIdx.x;    // 20
    int b  = threadIdx.x;   // 64
    float acc = 0.f;
    #pragma unroll 8
    for (int n = 0; n < 512; n++) acc += g_y1[n * BB + b] * W2[nc * 512 + n];
    out[b * NCLS + nc] = acc + b2[nc];
}

extern "C" void kernel_launch(void* const* d_in, const int* in_sizes, int n_in,
                              void* d_out, int out_size)
{
    const int*   text  = (const int*)d_in[0];
    const int*   label = (const int*)d_in[1];
    const float* emb   = (const float*)d_in[2];
    const float* cWihf = (const float*)d_in[3],  *cWhhf = (const float*)d_in[4];
    const float* cbihf = (const float*)d_in[5],  *cbhhf = (const float*)d_in[6];
    const float* cWihb = (const float*)d_in[7],  *cWhhb = (const float*)d_in[8];
    const float* cbihb = (const float*)d_in[9],  *cbhhb = (const float*)d_in[10];
    const float* mpw1  = (const float*)d_in[11], *mpw2  = (const float*)d_in[12];
    const float* aWihf = (const float*)d_in[13], *aWhhf = (const float*)d_in[14];
    const float* abihf = (const float*)d_in[15], *abhhf = (const float*)d_in[16];
    const float* aWihb = (const float*)d_in[17], *aWhhb = (const float*)d_in[18];
    const float* abihb = (const float*)d_in[19], *abhhb = (const float*)d_in[20];
    const float* W1    = (const float*)d_in[21], *b1    = (const float*)d_in[22];
    const float* W2    = (const float*)d_in[23], *b2    = (const float*)d_in[24];
    float* out = (float*)d_out;

    const int smem_gat = 256 * 65 * 4;                       //  66560 B
    const int smem_ctx = 16 * 512 * 4 + 128 * 64 * 16;       // 163840 B
    const int smem_agg = 16 * 256 * 4 + 64 * 64 * 16;        //  81920 B
    cudaFuncSetAttribute(gather_kernel, cudaFuncAttributeMaxDynamicSharedMemorySize, smem_gat);
    cudaFuncSetAttribute(ctx_persist,  cudaFuncAttributeMaxDynamicSharedMemorySize, smem_ctx);
    cudaFuncSetAttribute(agg_persist,  cudaFuncAttributeMaxDynamicSharedMemorySize, smem_agg);

    init_kernel<<<1, 128>>>();
    gather_kernel<<<TT + TL, 256, smem_gat>>>(text, label, emb);
    ctx_persist<<<128, 256, smem_ctx>>>(
        cWihf, cWhhf, cbihf, cbhhf, cWihb, cWhhb, cbihb, cbhhb);
    match_kernel<<<TT + TL, 64>>>(mpw1, mpw2);
    agg_persist<<<128, 256, smem_agg>>>(
        aWihf, aWhhf, abihf, abhhf, aWihb, aWhhb, abihb, abhhb);
    fc1_kernel<<<128, 256>>>(W1, b1);
    fc2_kernel<<<20, 64>>>(W2, b2, out);
}